// round 4
// baseline (speedup 1.0000x reference)
#include <cuda_runtime.h>
#include <cuda_fp16.h>
#include <cstdint>

// Problem dims
#define M_TOTAL 8192
#define K_TOTAL 4096
#define N_TOTAL 11008

// GEMM tiling
#define BM 128
#define BN 256
#define BK 64                       // 64 fp16 = 128B rows (SW128 atom)
#define NSTAGE 3
#define NCHUNK (K_TOTAL / BK)       // 64
#define THREADS 512                 // 16 warps: 4 (m) x 4 (n)
#define TILES_M (M_TOTAL / BM)      // 64
#define TILES_N (N_TOTAL / BN)      // 43
#define GRID (TILES_M * TILES_N)    // 2752

// SMEM layout
#define A_STAGE_BYTES (BM * 128)            // 16384
#define B_STAGE_BYTES (BN * 128)            // 32768
#define OFF_A 0                             // 3 * 16384 = 49152
#define OFF_B 49152                         // 3 * 32768
#define SMEM_DYN (49152 + 3 * 32768 + 1024) // + alignment slack = 148480

// fp16 scratch for converted operands (static device arrays: allocation-free)
__device__ __align__(16) __half g_A[(size_t)M_TOTAL * K_TOTAL];
__device__ __align__(16) __half g_B[(size_t)N_TOTAL * K_TOTAL];

__device__ __forceinline__ uint32_t smem_u32(const void* p) {
    return (uint32_t)__cvta_generic_to_shared(p);
}

// ---------------------------------------------------------------------------
// Conversion kernels: fp32 x -> fp16, int32 W -> fp16 (exact for |w|<=127)
// ---------------------------------------------------------------------------
__global__ void __launch_bounds__(256) convert_x_kernel(const float* __restrict__ x) {
    size_t i = (size_t)blockIdx.x * 256 + threadIdx.x;
    float4 v = reinterpret_cast<const float4*>(x)[i];
    __half2 h0 = __floats2half2_rn(v.x, v.y);
    __half2 h1 = __floats2half2_rn(v.z, v.w);
    uint2 u;
    u.x = *reinterpret_cast<uint32_t*>(&h0);
    u.y = *reinterpret_cast<uint32_t*>(&h1);
    reinterpret_cast<uint2*>(g_A)[i] = u;
}

__global__ void __launch_bounds__(256) convert_w_kernel(const int* __restrict__ w) {
    size_t i = (size_t)blockIdx.x * 256 + threadIdx.x;
    int4 v = reinterpret_cast<const int4*>(w)[i];
    __half2 h0 = __halves2half2(__int2half_rn(v.x), __int2half_rn(v.y));
    __half2 h1 = __halves2half2(__int2half_rn(v.z), __int2half_rn(v.w));
    uint2 u;
    u.x = *reinterpret_cast<uint32_t*>(&h0);
    u.y = *reinterpret_cast<uint32_t*>(&h1);
    reinterpret_cast<uint2*>(g_B)[i] = u;
}

// ---------------------------------------------------------------------------
// Stage loader: cp.async 16B chunks with SW128 swizzle (128B rows)
// swizzled(off) = off ^ ((off>>3)&0x70) ; for off = row*128 + c*16 this is
// row*128 + (c*16 ^ ((row&7)*16))
// ---------------------------------------------------------------------------
__device__ __forceinline__ void load_stage(
    uint32_t sbase, const __half* gA_tile, const __half* gB_tile,
    int chunk, int s, int tid)
{
    uint32_t sA = sbase + OFF_A + s * A_STAGE_BYTES;
    uint32_t sB = sbase + OFF_B + s * B_STAGE_BYTES;
    const char* gA = (const char*)gA_tile + (size_t)chunk * (BK * 2);
    const char* gB = (const char*)gB_tile + (size_t)chunk * (BK * 2);

    // A: 128 rows x 128B = 1024 x 16B chunks, 512 threads -> 2 iters
#pragma unroll
    for (int i = 0; i < 2; i++) {
        int idx = tid + (i << 9);
        int r = idx >> 3, c = idx & 7;
        const char* g = gA + (size_t)r * (K_TOTAL * 2) + (c << 4);
        uint32_t off = (uint32_t)(r << 7) + (uint32_t)(c << 4);
        uint32_t dst = sA + (off ^ ((off >> 3) & 0x70));
        asm volatile("cp.async.cg.shared.global [%0], [%1], 16;" :: "r"(dst), "l"(g));
    }
    // B: 256 rows x 128B = 2048 x 16B chunks -> 4 iters
#pragma unroll
    for (int i = 0; i < 4; i++) {
        int idx = tid + (i << 9);
        int r = idx >> 3, c = idx & 7;
        const char* g = gB + (size_t)r * (K_TOTAL * 2) + (c << 4);
        uint32_t off = (uint32_t)(r << 7) + (uint32_t)(c << 4);
        uint32_t dst = sB + (off ^ ((off >> 3) & 0x70));
        asm volatile("cp.async.cg.shared.global [%0], [%1], 16;" :: "r"(dst), "l"(g));
    }
    asm volatile("cp.async.commit_group;" ::: "memory");
}

// ---------------------------------------------------------------------------
// GEMM kernel: out[128,256] = A[128,K] fp16 @ B[256,K]^T fp16, fp32 accum
// (mma.sync m16n8k16: A row-major [m][k]; B "col-major" k x n == B[n][k] rows)
// epilogue: y = acc * scale[n] + bias[n]
// ---------------------------------------------------------------------------
__global__ void __launch_bounds__(THREADS, 1)
gemm_kernel(const float* __restrict__ scale, const float* __restrict__ bias,
            float* __restrict__ out)
{
    extern __shared__ char smem_raw[];
    char* smem = (char*)(((uintptr_t)smem_raw + 1023) & ~(uintptr_t)1023);
    uint32_t sbase = smem_u32(smem);
    int tid = threadIdx.x;
    int wid = tid >> 5, l = tid & 31;

    int m_tile = blockIdx.x % TILES_M;
    int n_tile = blockIdx.x / TILES_M;
    int m0 = m_tile * BM, n0 = n_tile * BN;

    const __half* gA_tile = g_A + (size_t)m0 * K_TOTAL;
    const __half* gB_tile = g_B + (size_t)n0 * K_TOTAL;

    // warp tile: 32 (m) x 64 (n); warp grid 4x4
    int wm0 = (wid >> 2) << 5;   // 0,32,64,96
    int wn0 = (wid & 3) << 6;    // 0,64,128,192

    // ldmatrix per-lane addressing constants (tile-relative)
    // A (x4, m16 x k16): lanes 0-15 -> rows base+l, k-half by lane>>4
    uint32_t rowA = (uint32_t)(wm0 + (l & 15));          // + mt*16
    uint32_t aOff[2], aC[2];
#pragma unroll
    for (int mt = 0; mt < 2; mt++) {
        uint32_t r = rowA + mt * 16;
        aOff[mt] = r << 7;
        aC[mt] = (r & 7) << 4;
    }
    uint32_t khA = (uint32_t)((l >> 4) << 4);            // 0 or 16 bytes

    // B (x4, n16 x k16): row = ng*16 + ((l>>4)&1)*8 + (l&7); k half = (l>>3)&1
    uint32_t bOff[4], bC[4];
#pragma unroll
    for (int ng = 0; ng < 4; ng++) {
        uint32_t r = (uint32_t)(wn0 + ng * 16 + (((l >> 4) & 1) << 3) + (l & 7));
        bOff[ng] = r << 7;
        bC[ng] = (r & 7) << 4;
    }
    uint32_t khB = (uint32_t)(((l >> 3) & 1) << 4);      // 0 or 16 bytes

    float acc[2][8][4];
#pragma unroll
    for (int mt = 0; mt < 2; mt++)
#pragma unroll
        for (int nt = 0; nt < 8; nt++)
#pragma unroll
            for (int c = 0; c < 4; c++) acc[mt][nt][c] = 0.0f;

    // prologue: fill first 2 stages
    load_stage(sbase, gA_tile, gB_tile, 0, 0, tid);
    load_stage(sbase, gA_tile, gB_tile, 1, 1, tid);

    // ---- mainloop over K chunks ----
    for (int k = 0; k < NCHUNK; k++) {
        int s = k % NSTAGE;

        if (k + 1 < NCHUNK)
            asm volatile("cp.async.wait_group 1;" ::: "memory");
        else
            asm volatile("cp.async.wait_group 0;" ::: "memory");
        __syncthreads();

        // refill stage (k+2)%3 for chunk k+2 (that stage was last read in iter k-1)
        int kn = k + NSTAGE - 1;
        if (kn < NCHUNK)
            load_stage(sbase, gA_tile, gB_tile, kn, kn % NSTAGE, tid);

        uint32_t sA = sbase + OFF_A + s * A_STAGE_BYTES;
        uint32_t sB = sbase + OFF_B + s * B_STAGE_BYTES;

#pragma unroll
        for (int step = 0; step < 4; step++) {
            uint32_t kbA = (uint32_t)(step << 5) + khA;   // step*32 + half*16
            uint32_t kbB = (uint32_t)(step << 5) + khB;

            uint32_t a[2][4];
#pragma unroll
            for (int mt = 0; mt < 2; mt++) {
                uint32_t addr = sA + aOff[mt] + (kbA ^ aC[mt]);
                asm volatile(
                    "ldmatrix.sync.aligned.m8n8.x4.shared.b16 {%0,%1,%2,%3}, [%4];"
                    : "=r"(a[mt][0]), "=r"(a[mt][1]), "=r"(a[mt][2]), "=r"(a[mt][3])
                    : "r"(addr));
            }
            uint32_t b[8][2];
#pragma unroll
            for (int ng = 0; ng < 4; ng++) {
                uint32_t addr = sB + bOff[ng] + (kbB ^ bC[ng]);
                asm volatile(
                    "ldmatrix.sync.aligned.m8n8.x4.shared.b16 {%0,%1,%2,%3}, [%4];"
                    : "=r"(b[2 * ng][0]), "=r"(b[2 * ng][1]),
                      "=r"(b[2 * ng + 1][0]), "=r"(b[2 * ng + 1][1])
                    : "r"(addr));
            }
#pragma unroll
            for (int mt = 0; mt < 2; mt++)
#pragma unroll
                for (int nt = 0; nt < 8; nt++) {
                    asm volatile(
                        "mma.sync.aligned.m16n8k16.row.col.f32.f16.f16.f32 "
                        "{%0,%1,%2,%3}, {%4,%5,%6,%7}, {%8,%9}, {%0,%1,%2,%3};"
                        : "+f"(acc[mt][nt][0]), "+f"(acc[mt][nt][1]),
                          "+f"(acc[mt][nt][2]), "+f"(acc[mt][nt][3])
                        : "r"(a[mt][0]), "r"(a[mt][1]), "r"(a[mt][2]), "r"(a[mt][3]),
                          "r"(b[nt][0]), "r"(b[nt][1]));
                }
        }
    }

    // ---- epilogue: scale/bias + float2 stores (4 lanes = one 32B sector) ----
#pragma unroll
    for (int mt = 0; mt < 2; mt++) {
        int mrow = m0 + wm0 + mt * 16 + (l >> 2);
#pragma unroll
        for (int nt = 0; nt < 8; nt++) {
            int ncol = n0 + wn0 + nt * 8 + ((l & 3) << 1);
            float2 sc = *reinterpret_cast<const float2*>(&scale[ncol]);
            float2 bi = *reinterpret_cast<const float2*>(&bias[ncol]);
            float2 v0, v1;
            v0.x = fmaf(acc[mt][nt][0], sc.x, bi.x);
            v0.y = fmaf(acc[mt][nt][1], sc.y, bi.y);
            v1.x = fmaf(acc[mt][nt][2], sc.x, bi.x);
            v1.y = fmaf(acc[mt][nt][3], sc.y, bi.y);
            *reinterpret_cast<float2*>(&out[(size_t)mrow * N_TOTAL + ncol]) = v0;
            *reinterpret_cast<float2*>(&out[(size_t)(mrow + 8) * N_TOTAL + ncol]) = v1;
        }
    }
}

// ---------------------------------------------------------------------------
// Launch
// ---------------------------------------------------------------------------
extern "C" void kernel_launch(void* const* d_in, const int* in_sizes, int n_in,
                              void* d_out, int out_size)
{
    const float* x     = (const float*)d_in[0];
    const int*   w     = (const int*)d_in[1];
    const float* scale = (const float*)d_in[2];
    const float* bias  = (const float*)d_in[3];
    float* out = (float*)d_out;

    convert_x_kernel<<<(unsigned)((size_t)M_TOTAL * K_TOTAL / 4 / 256), 256>>>(x);
    convert_w_kernel<<<(unsigned)((size_t)N_TOTAL * K_TOTAL / 4 / 256), 256>>>(w);

    cudaFuncSetAttribute(gemm_kernel,
                         cudaFuncAttributeMaxDynamicSharedMemorySize, SMEM_DYN);
    gemm_kernel<<<GRID, THREADS, SMEM_DYN>>>(scale, bias, out);
}

// round 6
// speedup vs baseline: 1.0199x; 1.0199x over previous
#include <cuda_runtime.h>
#include <cuda_fp16.h>
#include <cstdint>

// Problem dims
#define M_TOTAL 8192
#define K_TOTAL 4096
#define N_TOTAL 11008

// GEMM tiling
#define BM 128
#define BN 256
#define BK 64                       // 64 fp16 = 128B rows (SW128 atom)
#define NSTAGE 4
#define NCHUNK (K_TOTAL / BK)       // 64
#define THREADS 256                 // 8 warps: 2 (m) x 4 (n), warp tile 64x64
#define TILES_M (M_TOTAL / BM)      // 64
#define TILES_N (N_TOTAL / BN)      // 43
#define GRID (TILES_M * TILES_N)    // 2752

// SMEM layout
#define A_STAGE_BYTES (BM * 128)            // 16384
#define B_STAGE_BYTES (BN * 128)            // 32768
#define OFF_A 0                             // 4 * 16384 = 65536
#define OFF_B 65536                         // 4 * 32768 = 131072
#define SMEM_DYN (65536 + 4 * 32768 + 1024) // 197632 (< 227KB cap)

// fp16 scratch for converted operands (static device arrays: allocation-free)
__device__ __align__(16) __half g_A[(size_t)M_TOTAL * K_TOTAL];
__device__ __align__(16) __half g_B[(size_t)N_TOTAL * K_TOTAL];

__device__ __forceinline__ uint32_t smem_u32(const void* p) {
    return (uint32_t)__cvta_generic_to_shared(p);
}

// ---------------------------------------------------------------------------
// Conversion kernels: fp32 x -> fp16, int32 W -> fp16 (exact for |w|<=127)
// ---------------------------------------------------------------------------
__global__ void __launch_bounds__(256) convert_x_kernel(const float* __restrict__ x) {
    size_t i = (size_t)blockIdx.x * 256 + threadIdx.x;
    float4 v = reinterpret_cast<const float4*>(x)[i];
    __half2 h0 = __floats2half2_rn(v.x, v.y);
    __half2 h1 = __floats2half2_rn(v.z, v.w);
    uint2 u;
    u.x = *reinterpret_cast<uint32_t*>(&h0);
    u.y = *reinterpret_cast<uint32_t*>(&h1);
    reinterpret_cast<uint2*>(g_A)[i] = u;
}

__global__ void __launch_bounds__(256) convert_w_kernel(const int* __restrict__ w) {
    size_t i = (size_t)blockIdx.x * 256 + threadIdx.x;
    int4 v = reinterpret_cast<const int4*>(w)[i];
    __half2 h0 = __halves2half2(__int2half_rn(v.x), __int2half_rn(v.y));
    __half2 h1 = __halves2half2(__int2half_rn(v.z), __int2half_rn(v.w));
    uint2 u;
    u.x = *reinterpret_cast<uint32_t*>(&h0);
    u.y = *reinterpret_cast<uint32_t*>(&h1);
    reinterpret_cast<uint2*>(g_B)[i] = u;
}

// ---------------------------------------------------------------------------
// Stage loader: cp.async 16B chunks with SW128 swizzle (128B rows)
// swizzled(off) = off ^ ((off>>3)&0x70)
// ---------------------------------------------------------------------------
__device__ __forceinline__ void load_stage(
    uint32_t sbase, const __half* gA_tile, const __half* gB_tile,
    int chunk, int s, int tid)
{
    uint32_t sA = sbase + OFF_A + s * A_STAGE_BYTES;
    uint32_t sB = sbase + OFF_B + s * B_STAGE_BYTES;
    const char* gA = (const char*)gA_tile + (size_t)chunk * (BK * 2);
    const char* gB = (const char*)gB_tile + (size_t)chunk * (BK * 2);

    // A: 128 rows x 128B = 1024 x 16B chunks, 256 threads -> 4 iters
#pragma unroll
    for (int i = 0; i < 4; i++) {
        int idx = tid + (i << 8);
        int r = idx >> 3, c = idx & 7;
        const char* g = gA + (size_t)r * (K_TOTAL * 2) + (c << 4);
        uint32_t off = (uint32_t)(r << 7) + (uint32_t)(c << 4);
        uint32_t dst = sA + (off ^ ((off >> 3) & 0x70));
        asm volatile("cp.async.cg.shared.global [%0], [%1], 16;" :: "r"(dst), "l"(g));
    }
    // B: 256 rows x 128B = 2048 x 16B chunks -> 8 iters
#pragma unroll
    for (int i = 0; i < 8; i++) {
        int idx = tid + (i << 8);
        int r = idx >> 3, c = idx & 7;
        const char* g = gB + (size_t)r * (K_TOTAL * 2) + (c << 4);
        uint32_t off = (uint32_t)(r << 7) + (uint32_t)(c << 4);
        uint32_t dst = sB + (off ^ ((off >> 3) & 0x70));
        asm volatile("cp.async.cg.shared.global [%0], [%1], 16;" :: "r"(dst), "l"(g));
    }
    asm volatile("cp.async.commit_group;" ::: "memory");
}

// ---------------------------------------------------------------------------
// GEMM kernel: out[128,256] = A[128,K] fp16 @ B[256,K]^T fp16, fp32 accum
// 8 warps, warp tile 64x64; mma.sync m16n8k16 (A row-major, B [n][k] rows)
// epilogue: y = acc * scale[n] + bias[n]
// ---------------------------------------------------------------------------
__global__ void __launch_bounds__(THREADS, 1)
gemm_kernel(const float* __restrict__ scale, const float* __restrict__ bias,
            float* __restrict__ out)
{
    extern __shared__ char smem_raw[];
    char* smem = (char*)(((uintptr_t)smem_raw + 1023) & ~(uintptr_t)1023);
    uint32_t sbase = smem_u32(smem);
    int tid = threadIdx.x;
    int wid = tid >> 5, l = tid & 31;

    int m_tile = blockIdx.x % TILES_M;
    int n_tile = blockIdx.x / TILES_M;
    int m0 = m_tile * BM, n0 = n_tile * BN;

    const __half* gA_tile = g_A + (size_t)m0 * K_TOTAL;
    const __half* gB_tile = g_B + (size_t)n0 * K_TOTAL;

    // warp tile: 64 (m) x 64 (n); warp grid 2x4
    int wm0 = (wid >> 2) << 6;   // 0,64
    int wn0 = (wid & 3) << 6;    // 0,64,128,192

    // A (x4, m16 x k16): lanes 0-15 -> rows base+(l&15), k-half by lane>>4
    uint32_t aOff[4], aC[4];
#pragma unroll
    for (int mt = 0; mt < 4; mt++) {
        uint32_t r = (uint32_t)(wm0 + mt * 16 + (l & 15));
        aOff[mt] = r << 7;
        aC[mt] = (r & 7) << 4;
    }
    uint32_t khA = (uint32_t)((l >> 4) << 4);            // 0 or 16 bytes

    // B (x4, n16 x k16): row = ng*16 + ((l>>4)&1)*8 + (l&7); k half = (l>>3)&1
    uint32_t bOff[4], bC[4];
#pragma unroll
    for (int ng = 0; ng < 4; ng++) {
        uint32_t r = (uint32_t)(wn0 + ng * 16 + (((l >> 4) & 1) << 3) + (l & 7));
        bOff[ng] = r << 7;
        bC[ng] = (r & 7) << 4;
    }
    uint32_t khB = (uint32_t)(((l >> 3) & 1) << 4);      // 0 or 16 bytes

    float acc[4][8][4];
#pragma unroll
    for (int mt = 0; mt < 4; mt++)
#pragma unroll
        for (int nt = 0; nt < 8; nt++)
#pragma unroll
            for (int c = 0; c < 4; c++) acc[mt][nt][c] = 0.0f;

    // prologue: fill first NSTAGE-1 stages
    load_stage(sbase, gA_tile, gB_tile, 0, 0, tid);
    load_stage(sbase, gA_tile, gB_tile, 1, 1, tid);
    load_stage(sbase, gA_tile, gB_tile, 2, 2, tid);

    // ---- mainloop over K chunks ----
    for (int k = 0; k < NCHUNK; k++) {
        int s = k & 3;

        // retire chunk k's cp.async group
        if (k + 2 < NCHUNK)
            asm volatile("cp.async.wait_group 2;" ::: "memory");
        else if (k + 1 < NCHUNK)
            asm volatile("cp.async.wait_group 1;" ::: "memory");
        else
            asm volatile("cp.async.wait_group 0;" ::: "memory");
        __syncthreads();

        // refill stage (k+3)&3 (last read in iter k-1) with chunk k+3
        int kn = k + NSTAGE - 1;
        if (kn < NCHUNK)
            load_stage(sbase, gA_tile, gB_tile, kn, kn & 3, tid);

        uint32_t sA = sbase + OFF_A + s * A_STAGE_BYTES;
        uint32_t sB = sbase + OFF_B + s * B_STAGE_BYTES;

#pragma unroll
        for (int step = 0; step < 4; step++) {
            uint32_t kbA = (uint32_t)(step << 5) + khA;   // step*32 + half*16
            uint32_t kbB = (uint32_t)(step << 5) + khB;

            uint32_t a[4][4];
#pragma unroll
            for (int mt = 0; mt < 4; mt++) {
                uint32_t addr = sA + aOff[mt] + (kbA ^ aC[mt]);
                asm volatile(
                    "ldmatrix.sync.aligned.m8n8.x4.shared.b16 {%0,%1,%2,%3}, [%4];"
                    : "=r"(a[mt][0]), "=r"(a[mt][1]), "=r"(a[mt][2]), "=r"(a[mt][3])
                    : "r"(addr));
            }
            uint32_t b[8][2];
#pragma unroll
            for (int ng = 0; ng < 4; ng++) {
                uint32_t addr = sB + bOff[ng] + (kbB ^ bC[ng]);
                asm volatile(
                    "ldmatrix.sync.aligned.m8n8.x4.shared.b16 {%0,%1,%2,%3}, [%4];"
                    : "=r"(b[2 * ng][0]), "=r"(b[2 * ng][1]),
                      "=r"(b[2 * ng + 1][0]), "=r"(b[2 * ng + 1][1])
                    : "r"(addr));
            }
#pragma unroll
            for (int mt = 0; mt < 4; mt++)
#pragma unroll
                for (int nt = 0; nt < 8; nt++) {
                    asm volatile(
                        "mma.sync.aligned.m16n8k16.row.col.f32.f16.f16.f32 "
                        "{%0,%1,%2,%3}, {%4,%5,%6,%7}, {%8,%9}, {%0,%1,%2,%3};"
                        : "+f"(acc[mt][nt][0]), "+f"(acc[mt][nt][1]),
                          "+f"(acc[mt][nt][2]), "+f"(acc[mt][nt][3])
                        : "r"(a[mt][0]), "r"(a[mt][1]), "r"(a[mt][2]), "r"(a[mt][3]),
                          "r"(b[nt][0]), "r"(b[nt][1]));
                }
        }
    }

    // ---- epilogue: scale/bias + float2 stores (4 lanes = one 32B sector) ----
#pragma unroll
    for (int mt = 0; mt < 4; mt++) {
        int mrow = m0 + wm0 + mt * 16 + (l >> 2);
#pragma unroll
        for (int nt = 0; nt < 8; nt++) {
            int ncol = n0 + wn0 + nt * 8 + ((l & 3) << 1);
            float2 sc = *reinterpret_cast<const float2*>(&scale[ncol]);
            float2 bi = *reinterpret_cast<const float2*>(&bias[ncol]);
            float2 v0, v1;
            v0.x = fmaf(acc[mt][nt][0], sc.x, bi.x);
            v0.y = fmaf(acc[mt][nt][1], sc.y, bi.y);
            v1.x = fmaf(acc[mt][nt][2], sc.x, bi.x);
            v1.y = fmaf(acc[mt][nt][3], sc.y, bi.y);
            *reinterpret_cast<float2*>(&out[(size_t)mrow * N_TOTAL + ncol]) = v0;
            *reinterpret_cast<float2*>(&out[(size_t)(mrow + 8) * N_TOTAL + ncol]) = v1;
        }
    }
}

// ---------------------------------------------------------------------------
// Launch
// ---------------------------------------------------------------------------
extern "C" void kernel_launch(void* const* d_in, const int* in_sizes, int n_in,
                              void* d_out, int out_size)
{
    const float* x     = (const float*)d_in[0];
    const int*   w     = (const int*)d_in[1];
    const float* scale = (const float*)d_in[2];
    const float* bias  = (const float*)d_in[3];
    float* out = (float*)d_out;

    convert_x_kernel<<<(unsigned)((size_t)M_TOTAL * K_TOTAL / 4 / 256), 256>>>(x);
    convert_w_kernel<<<(unsigned)((size_t)N_TOTAL * K_TOTAL / 4 / 256), 256>>>(w);

    cudaFuncSetAttribute(gemm_kernel,
                         cudaFuncAttributeMaxDynamicSharedMemorySize, SMEM_DYN);
    gemm_kernel<<<GRID, THREADS, SMEM_DYN>>>(scale, bias, out);
}

// round 7
// speedup vs baseline: 1.0957x; 1.0743x over previous
#include <cuda_runtime.h>
#include <cuda_fp16.h>
#include <cstdint>

// Problem dims
#define M_TOTAL 8192
#define K_TOTAL 4096
#define N_TOTAL 11008

// GEMM tiling
#define BM 128
#define BN 256
#define BK 64                       // 64 fp16 = 128B rows (SW128 atom)
#define NSTAGE 4
#define NCHUNK (K_TOTAL / BK)       // 64
#define THREADS 256                 // 8 warps: 2 (m) x 4 (n), warp tile 64x64
#define TILES_M (M_TOTAL / BM)      // 64
#define TILES_N (N_TOTAL / BN)      // 43
#define GRID (TILES_M * TILES_N)    // 2752
#define GROUP_M 8                   // bid swizzle: 8 m-tiles per supergroup

// SMEM layout
#define A_STAGE_BYTES (BM * 128)            // 16384
#define B_STAGE_BYTES (BN * 128)            // 32768
#define OFF_A 0                             // 4 * 16384 = 65536
#define OFF_B 65536                         // 4 * 32768 = 131072
#define SMEM_DYN (65536 + 4 * 32768 + 1024) // 197632 (< 227KB cap)

// fp16 scratch for converted operands (static device arrays: allocation-free)
__device__ __align__(16) __half g_A[(size_t)M_TOTAL * K_TOTAL];
__device__ __align__(16) __half g_B[(size_t)N_TOTAL * K_TOTAL];

__device__ __forceinline__ uint32_t smem_u32(const void* p) {
    return (uint32_t)__cvta_generic_to_shared(p);
}

// ---------------------------------------------------------------------------
// Conversion kernels: fp32 x -> fp16, int32 W -> fp16 (exact for |w|<=127)
// ---------------------------------------------------------------------------
__global__ void __launch_bounds__(256) convert_x_kernel(const float* __restrict__ x) {
    size_t i = (size_t)blockIdx.x * 256 + threadIdx.x;
    float4 v = reinterpret_cast<const float4*>(x)[i];
    __half2 h0 = __floats2half2_rn(v.x, v.y);
    __half2 h1 = __floats2half2_rn(v.z, v.w);
    uint2 u;
    u.x = *reinterpret_cast<uint32_t*>(&h0);
    u.y = *reinterpret_cast<uint32_t*>(&h1);
    reinterpret_cast<uint2*>(g_A)[i] = u;
}

__global__ void __launch_bounds__(256) convert_w_kernel(const int* __restrict__ w) {
    size_t i = (size_t)blockIdx.x * 256 + threadIdx.x;
    int4 v = reinterpret_cast<const int4*>(w)[i];
    __half2 h0 = __halves2half2(__int2half_rn(v.x), __int2half_rn(v.y));
    __half2 h1 = __halves2half2(__int2half_rn(v.z), __int2half_rn(v.w));
    uint2 u;
    u.x = *reinterpret_cast<uint32_t*>(&h0);
    u.y = *reinterpret_cast<uint32_t*>(&h1);
    reinterpret_cast<uint2*>(g_B)[i] = u;
}

// ---------------------------------------------------------------------------
// Stage loader: cp.async 16B chunks with SW128 swizzle (128B rows)
// ---------------------------------------------------------------------------
__device__ __forceinline__ void load_stage(
    uint32_t sbase, const __half* gA_tile, const __half* gB_tile,
    int chunk, int s, int tid)
{
    uint32_t sA = sbase + OFF_A + s * A_STAGE_BYTES;
    uint32_t sB = sbase + OFF_B + s * B_STAGE_BYTES;
    const char* gA = (const char*)gA_tile + (size_t)chunk * (BK * 2);
    const char* gB = (const char*)gB_tile + (size_t)chunk * (BK * 2);

#pragma unroll
    for (int i = 0; i < 4; i++) {
        int idx = tid + (i << 8);
        int r = idx >> 3, c = idx & 7;
        const char* g = gA + (size_t)r * (K_TOTAL * 2) + (c << 4);
        uint32_t off = (uint32_t)(r << 7) + (uint32_t)(c << 4);
        uint32_t dst = sA + (off ^ ((off >> 3) & 0x70));
        asm volatile("cp.async.cg.shared.global [%0], [%1], 16;" :: "r"(dst), "l"(g));
    }
#pragma unroll
    for (int i = 0; i < 8; i++) {
        int idx = tid + (i << 8);
        int r = idx >> 3, c = idx & 7;
        const char* g = gB + (size_t)r * (K_TOTAL * 2) + (c << 4);
        uint32_t off = (uint32_t)(r << 7) + (uint32_t)(c << 4);
        uint32_t dst = sB + (off ^ ((off >> 3) & 0x70));
        asm volatile("cp.async.cg.shared.global [%0], [%1], 16;" :: "r"(dst), "l"(g));
    }
    asm volatile("cp.async.commit_group;" ::: "memory");
}

// ---------------------------------------------------------------------------
// Fragment loader: 4x A ldmatrix.x4 + 4x B ldmatrix.x4 for one k16 step
// a[16]: a[mt*4+i]; b[16]: b[nt*2+h]
// ---------------------------------------------------------------------------
__device__ __forceinline__ void load_frags(
    uint32_t* a, uint32_t* b, uint32_t sA, uint32_t sB, int step,
    const uint32_t* aOff, const uint32_t* aC,
    const uint32_t* bOff, const uint32_t* bC,
    uint32_t khA, uint32_t khB)
{
    uint32_t kbA = (uint32_t)(step << 5) + khA;
    uint32_t kbB = (uint32_t)(step << 5) + khB;
#pragma unroll
    for (int mt = 0; mt < 4; mt++) {
        uint32_t addr = sA + aOff[mt] + (kbA ^ aC[mt]);
        asm volatile(
            "ldmatrix.sync.aligned.m8n8.x4.shared.b16 {%0,%1,%2,%3}, [%4];"
            : "=r"(a[mt * 4 + 0]), "=r"(a[mt * 4 + 1]),
              "=r"(a[mt * 4 + 2]), "=r"(a[mt * 4 + 3])
            : "r"(addr));
    }
#pragma unroll
    for (int ng = 0; ng < 4; ng++) {
        uint32_t addr = sB + bOff[ng] + (kbB ^ bC[ng]);
        asm volatile(
            "ldmatrix.sync.aligned.m8n8.x4.shared.b16 {%0,%1,%2,%3}, [%4];"
            : "=r"(b[ng * 4 + 0]), "=r"(b[ng * 4 + 1]),
              "=r"(b[ng * 4 + 2]), "=r"(b[ng * 4 + 3])
            : "r"(addr));
    }
}

// ---------------------------------------------------------------------------
// GEMM kernel: out[128,256] = A[128,K] fp16 @ B[256,K]^T fp16, fp32 accum
// 8 warps, warp tile 64x64; software-pipelined fragments across barriers
// ---------------------------------------------------------------------------
__global__ void __launch_bounds__(THREADS, 1)
gemm_kernel(const float* __restrict__ scale, const float* __restrict__ bias,
            float* __restrict__ out)
{
    extern __shared__ char smem_raw[];
    char* smem = (char*)(((uintptr_t)smem_raw + 1023) & ~(uintptr_t)1023);
    uint32_t sbase = smem_u32(smem);
    int tid = threadIdx.x;
    int wid = tid >> 5, l = tid & 31;

    // bid swizzle: supergroups of 8 m-tiles x all 43 n-tiles (wave locality)
    int bid = blockIdx.x;
    int grp = bid / (GROUP_M * TILES_N);
    int rem = bid % (GROUP_M * TILES_N);
    int m_tile = grp * GROUP_M + (rem % GROUP_M);
    int n_tile = rem / GROUP_M;
    int m0 = m_tile * BM, n0 = n_tile * BN;

    const __half* gA_tile = g_A + (size_t)m0 * K_TOTAL;
    const __half* gB_tile = g_B + (size_t)n0 * K_TOTAL;

    // warp tile: 64 (m) x 64 (n); warp grid 2x4
    int wm0 = (wid >> 2) << 6;
    int wn0 = (wid & 3) << 6;

    uint32_t aOff[4], aC[4];
#pragma unroll
    for (int mt = 0; mt < 4; mt++) {
        uint32_t r = (uint32_t)(wm0 + mt * 16 + (l & 15));
        aOff[mt] = r << 7;
        aC[mt] = (r & 7) << 4;
    }
    uint32_t khA = (uint32_t)((l >> 4) << 4);

    uint32_t bOff[4], bC[4];
#pragma unroll
    for (int ng = 0; ng < 4; ng++) {
        uint32_t r = (uint32_t)(wn0 + ng * 16 + (((l >> 4) & 1) << 3) + (l & 7));
        bOff[ng] = r << 7;
        bC[ng] = (r & 7) << 4;
    }
    uint32_t khB = (uint32_t)(((l >> 3) & 1) << 4);

    float acc[4][8][4];
#pragma unroll
    for (int mt = 0; mt < 4; mt++)
#pragma unroll
        for (int nt = 0; nt < 8; nt++)
#pragma unroll
            for (int c = 0; c < 4; c++) acc[mt][nt][c] = 0.0f;

    // double-buffered fragments
    uint32_t bufA[2][16], bufB[2][16];

    // prologue: stages 0..2; retire chunks 0,1; stage 3; first fragments
    load_stage(sbase, gA_tile, gB_tile, 0, 0, tid);
    load_stage(sbase, gA_tile, gB_tile, 1, 1, tid);
    load_stage(sbase, gA_tile, gB_tile, 2, 2, tid);
    asm volatile("cp.async.wait_group 1;" ::: "memory");
    __syncthreads();
    load_stage(sbase, gA_tile, gB_tile, 3, 3, tid);
    load_frags(bufA[0], bufB[0], sbase + OFF_A, sbase + OFF_B, 0,
               aOff, aC, bOff, bC, khA, khB);

    // ---- mainloop ----
    for (int k = 0; k < NCHUNK; k++) {
        uint32_t sA  = sbase + OFF_A + (k & 3) * A_STAGE_BYTES;
        uint32_t sB  = sbase + OFF_B + (k & 3) * B_STAGE_BYTES;
        uint32_t sA1 = sbase + OFF_A + ((k + 1) & 3) * A_STAGE_BYTES;
        uint32_t sB1 = sbase + OFF_B + ((k + 1) & 3) * B_STAGE_BYTES;

#pragma unroll
        for (int step = 0; step < 4; step++) {
            const int cur = step & 1, nxt = cur ^ 1;
            // prefetch next fragments (next step, or next chunk's step 0 —
            // its cp.async group was retired by the previous wait_group 1,
            // and made CTA-visible by the previous __syncthreads)
            if (step < 3) {
                load_frags(bufA[nxt], bufB[nxt], sA, sB, step + 1,
                           aOff, aC, bOff, bC, khA, khB);
            } else if (k + 1 < NCHUNK) {
                load_frags(bufA[nxt], bufB[nxt], sA1, sB1, 0,
                           aOff, aC, bOff, bC, khA, khB);
            }
#pragma unroll
            for (int mt = 0; mt < 4; mt++)
#pragma unroll
                for (int nt = 0; nt < 8; nt++) {
                    asm volatile(
                        "mma.sync.aligned.m16n8k16.row.col.f32.f16.f16.f32 "
                        "{%0,%1,%2,%3}, {%4,%5,%6,%7}, {%8,%9}, {%0,%1,%2,%3};"
                        : "+f"(acc[mt][nt][0]), "+f"(acc[mt][nt][1]),
                          "+f"(acc[mt][nt][2]), "+f"(acc[mt][nt][3])
                        : "r"(bufA[cur][mt * 4 + 0]), "r"(bufA[cur][mt * 4 + 1]),
                          "r"(bufA[cur][mt * 4 + 2]), "r"(bufA[cur][mt * 4 + 3]),
                          "r"(bufB[cur][nt * 2]),     "r"(bufB[cur][nt * 2 + 1]));
                }
        }

        if (k + 1 < NCHUNK) {
            // retire through chunk k+2 (needed for iter k+1's own prefetch)
            if (k + 3 < NCHUNK)
                asm volatile("cp.async.wait_group 1;" ::: "memory");
            else
                asm volatile("cp.async.wait_group 0;" ::: "memory");
            __syncthreads();
            if (k + 4 < NCHUNK)
                load_stage(sbase, gA_tile, gB_tile, k + 4, (k + 4) & 3, tid);
        }
    }

    // ---- epilogue: scale/bias + float2 stores ----
#pragma unroll
    for (int mt = 0; mt < 4; mt++) {
        int mrow = m0 + wm0 + mt * 16 + (l >> 2);
#pragma unroll
        for (int nt = 0; nt < 8; nt++) {
            int ncol = n0 + wn0 + nt * 8 + ((l & 3) << 1);
            float2 sc = *reinterpret_cast<const float2*>(&scale[ncol]);
            float2 bi = *reinterpret_cast<const float2*>(&bias[ncol]);
            float2 v0, v1;
            v0.x = fmaf(acc[mt][nt][0], sc.x, bi.x);
            v0.y = fmaf(acc[mt][nt][1], sc.y, bi.y);
            v1.x = fmaf(acc[mt][nt][2], sc.x, bi.x);
            v1.y = fmaf(acc[mt][nt][3], sc.y, bi.y);
            *reinterpret_cast<float2*>(&out[(size_t)mrow * N_TOTAL + ncol]) = v0;
            *reinterpret_cast<float2*>(&out[(size_t)(mrow + 8) * N_TOTAL + ncol]) = v1;
        }
    }
}

// ---------------------------------------------------------------------------
// Launch
// ---------------------------------------------------------------------------
extern "C" void kernel_launch(void* const* d_in, const int* in_sizes, int n_in,
                              void* d_out, int out_size)
{
    const float* x     = (const float*)d_in[0];
    const int*   w     = (const int*)d_in[1];
    const float* scale = (const float*)d_in[2];
    const float* bias  = (const float*)d_in[3];
    float* out = (float*)d_out;

    convert_x_kernel<<<(unsigned)((size_t)M_TOTAL * K_TOTAL / 4 / 256), 256>>>(x);
    convert_w_kernel<<<(unsigned)((size_t)N_TOTAL * K_TOTAL / 4 / 256), 256>>>(w);

    cudaFuncSetAttribute(gemm_kernel,
                         cudaFuncAttributeMaxDynamicSharedMemorySize, SMEM_DYN);
    gemm_kernel<<<GRID, THREADS, SMEM_DYN>>>(scale, bias, out);
}